// round 16
// baseline (speedup 1.0000x reference)
#include <cuda_runtime.h>
#include <cstdint>

#define NB    128
#define TPB   512
#define HID   512
#define BAT   128
#define T_IN  512
#define TT    544          // T_IN + future(32)

// smem layout (float offsets)
#define OW1   0            // W_hh1^T  [512][20] (16 rows used, stride 20 conflict-free)
#define OW2   10240        // W_ih2^T
#define OW3   20480        // W_hh2^T
#define OHB   30720        // warp staging: 16 warps x 4 bufs x 256 floats
#define OGA   47104        // gate buffer layer1 [16][128]
#define OGB   49152        // gate buffer layer2 [16][128]
#define OC1   51200        // c1 state [4][128]
#define OC2   51712        // c2 state [4][128]
#define OCB1  52224        // bias1 [16]
#define OCW1  52240        // wih1  [16]
#define OCB2  52256        // bias2 [16]
#define OCWO  52272        // wout  [4]
#define SMF   52288        // 209,152 bytes

__device__ float    g_h1[3][HID * BAT];   // h1(t) lives in slot t%3
__device__ float    g_h2[3][HID * BAT];   // h2(t) lives in slot t%3
__device__ unsigned g_bar1;               // publishes h1(r); arrive mid-region
__device__ unsigned g_bar2;               // publishes h2(r-1)+out(r-1); arrive at end

using ull = unsigned long long;

__device__ __forceinline__ ull pk2(float w) {
    ull r; asm("mov.b64 %0, {%1, %1};" : "=l"(r) : "f"(w)); return r;
}
__device__ __forceinline__ void fma2(ull &a, ull w, ull h) {
    asm("fma.rn.f32x2 %0, %1, %2, %0;" : "+l"(a) : "l"(w), "l"(h));
}
__device__ __forceinline__ ull add2(ull a, ull b) {
    ull r; asm("add.rn.f32x2 %0, %1, %2;" : "=l"(r) : "l"(a), "l"(b)); return r;
}
__device__ __forceinline__ float2 unpk(ull v) {
    float2 f; asm("mov.b64 {%0, %1}, %2;" : "=f"(f.x), "=f"(f.y) : "l"(v)); return f;
}
__device__ __forceinline__ void cp16(float* dst, const float* src) {
    unsigned d = (unsigned)__cvta_generic_to_shared(dst);
    asm volatile("cp.async.cg.shared.global [%0], [%1], 16;" :: "r"(d), "l"(src));
}
__device__ __forceinline__ float ldcg32(const float* p) {
    float v;
    asm volatile("ld.global.cg.f32 %0, [%1];" : "=f"(v) : "l"(p));
    return v;
}
__device__ __forceinline__ float sigf(float v) { return 1.0f / (1.0f + expf(-v)); }

// split barrier: arrive (release) / wait (acquire). All 128 blocks co-resident.
__device__ __forceinline__ void bar_arrive(unsigned* ctr) {
    __threadfence();          // each writer pushes its stores to GPU scope
    __syncthreads();          // all writers fenced before the release add
    if (threadIdx.x == 0) atomicAdd(ctr, 1u);
}
__device__ __forceinline__ void bar_wait(unsigned* ctr, unsigned target) {
    if (threadIdx.x == 0) {
        unsigned v;
        do {
            asm volatile("ld.acquire.gpu.global.u32 %0, [%1];"
                         : "=r"(v) : "l"(ctr) : "memory");
        } while (v < target);
    }
    __syncthreads();
    __threadfence();
}

// One K=512 pass, warp-independent. 16 chunks of 32 k; 4-deep cp.async ring
// (wait_group 2 -> commit-to-wait gap = 3 chunk computes, covers L2 latency).
// Chunk buffer layout (256 floats): plane0[32 rows][batches 0-3],
// plane1[32 rows][batches 4-7] -> every LDS.128 is 16 lanes x 16B contiguous
// (conflict-free, broadcast to the upper half-warp).
__device__ __forceinline__ void pass_accum(
    const float* __restrict__ hsrc,   // global [512][128]
    const float* __restrict__ wT,     // smem k-major [512][20]
    float* __restrict__ wb,           // warp staging (4 x 256 floats)
    ull acc[8][4], int rg8, int bg8, int slice, int lane)
{
    const int idx = lane;             // each lane stages 2 x 16B per chunk
    #pragma unroll
    for (int c0 = 0; c0 < 3; c0++) {  // prologue: chunks 0..2 in flight
        float* dstb = wb + (c0 << 8);
        #pragma unroll
        for (int q = 0; q < 2; q++) {
            int id = idx + (q << 5);
            int row = id >> 1, j = id & 1;
            cp16(dstb + (j << 7) + (row << 2),
                 hsrc + (((c0 << 5) + row) << 7) + bg8 + (j << 2));
        }
        asm volatile("cp.async.commit_group;");
    }

    #pragma unroll 1
    for (int c = 0; c < 16; c++) {
        if (c < 14)       asm volatile("cp.async.wait_group 2;");
        else if (c == 14) asm volatile("cp.async.wait_group 1;");
        else              asm volatile("cp.async.wait_group 0;");
        __syncwarp();

        const float* cur = wb + ((c & 3) << 8);
        #pragma unroll
        for (int ii = 0; ii < 2; ii++) {
            int kl = (ii << 4) + slice;
            ulonglong2 ha = *reinterpret_cast<const ulonglong2*>(cur + (kl << 2));
            ulonglong2 hc = *reinterpret_cast<const ulonglong2*>(cur + 128 + (kl << 2));
            ull hv[4] = { ha.x, ha.y, hc.x, hc.y };

            int kg = (c << 5) + kl;
            const float* wk = wT + kg * 20 + rg8;
            float4 w0 = *reinterpret_cast<const float4*>(wk);
            {
                ull wr[4] = { pk2(w0.x), pk2(w0.y), pk2(w0.z), pk2(w0.w) };
                #pragma unroll
                for (int r = 0; r < 4; r++)
                    #pragma unroll
                    for (int p = 0; p < 4; p++)
                        fma2(acc[r][p], wr[r], hv[p]);
            }
            float4 w1 = *reinterpret_cast<const float4*>(wk + 4);
            {
                ull wr[4] = { pk2(w1.x), pk2(w1.y), pk2(w1.z), pk2(w1.w) };
                #pragma unroll
                for (int r = 0; r < 4; r++)
                    #pragma unroll
                    for (int p = 0; p < 4; p++)
                        fma2(acc[4 + r][p], wr[r], hv[p]);
            }
        }

        if (c < 13) {   // stage chunk c+3 (overwrites buffer of chunk c-1: safe,
                        // its reads finished last iteration in convergent code)
            float* nx = wb + (((c + 3) & 3) << 8);
            const float* s = hsrc + (((c + 3) << 5) << 7);
            #pragma unroll
            for (int q = 0; q < 2; q++) {
                int id = idx + (q << 5);
                int row = id >> 1, j = id & 1;
                cp16(nx + (j << 7) + (row << 2), s + (row << 7) + bg8 + (j << 2));
            }
            asm volatile("cp.async.commit_group;");
        }
    }
}

// Distributed butterfly reduction over the 16 k-slices (lane bits 0-3).
__device__ __forceinline__ void reduce_to_gbuf(
    ull acc[8][4], float* gbuf, int rg8, int bg8, int lane)
{
    ull* v = &acc[0][0];
    int live = 32;
    #pragma unroll
    for (int m = 0; m < 4; m++) {
        int half = live >> 1;
        int mask = 1 << m;
        bool hi = (lane >> m) & 1;
        #pragma unroll
        for (int j = 0; j < half; j++) {
            ull lo_s = add2(v[j],        __shfl_xor_sync(0xffffffffu, v[j],        mask));
            ull hi_s = add2(v[j + half], __shfl_xor_sync(0xffffffffu, v[j + half], mask));
            v[j] = hi ? hi_s : lo_s;
        }
        live = half;
    }
    int s = lane & 15;
    int base = ((s & 1) << 4) | (((s >> 1) & 1) << 3) |
               (((s >> 2) & 1) << 2) | (((s >> 3) & 1) << 1);
    #pragma unroll
    for (int j = 0; j < 2; j++) {
        int i = base + j;
        float2 f = unpk(v[j]);
        *reinterpret_cast<float2*>(gbuf + (rg8 + (i >> 2)) * BAT + bg8 + 2 * (i & 3)) = f;
    }
}

__global__ void init_kernel(float* __restrict__ out, const float* __restrict__ b_out) {
    int i = blockIdx.x * blockDim.x + threadIdx.x;
    if (i == 0) { g_bar1 = 0u; g_bar2 = 0u; }
    if (i < HID * BAT) {
        g_h1[0][i] = 0.0f; g_h1[1][i] = 0.0f; g_h1[2][i] = 0.0f;
        g_h2[0][i] = 0.0f; g_h2[1][i] = 0.0f; g_h2[2][i] = 0.0f;
    }
    if (i < BAT * TT) out[i] = b_out[0];
}

__global__ void __launch_bounds__(TPB, 1)
lstm_persistent_kernel(
    const float* __restrict__ x,
    const float* __restrict__ W_ih1, const float* __restrict__ W_hh1,
    const float* __restrict__ b_ih1, const float* __restrict__ b_hh1,
    const float* __restrict__ W_ih2, const float* __restrict__ W_hh2,
    const float* __restrict__ b_ih2, const float* __restrict__ b_hh2,
    const float* __restrict__ W_out, float* __restrict__ out)
{
    extern __shared__ float sm[];
    const int tid  = threadIdx.x;
    const int blk  = blockIdx.x;
    const int lane = tid & 31;
    const int warp = tid >> 5;          // 16 warps

    const int slice = lane & 15;        // k-slice (16-way)
    const int rg8   = (lane >> 4) << 3; // row base: 0 or 8
    const int bg8   = warp << 3;        // batch base (warp-uniform)

    const int cu = tid >> 7;            // cell-update unit 0..3
    const int cb = tid & 127;           // cell-update batch

    // ---- one-time setup
    for (int idx = tid; idx < 16 * HID; idx += TPB) {
        int r = idx >> 9, k = idx & 511;               // r = gate*4 + unit
        int row = ((r >> 2) * HID) + blk * 4 + (r & 3);
        sm[OW1 + k * 20 + r] = W_hh1[row * HID + k];
        sm[OW2 + k * 20 + r] = W_ih2[row * HID + k];
        sm[OW3 + k * 20 + r] = W_hh2[row * HID + k];
    }
    if (tid < 16) {
        int row = ((tid >> 2) * HID) + blk * 4 + (tid & 3);
        sm[OCB1 + tid] = b_ih1[row] + b_hh1[row];
        sm[OCW1 + tid] = W_ih1[row];                   // F = 1
        sm[OCB2 + tid] = b_ih2[row] + b_hh2[row];
    }
    if (tid < 4) sm[OCWO + tid] = W_out[blk * 4 + tid];
    for (int idx = tid; idx < 4 * BAT; idx += TPB) {
        sm[OC1 + idx] = 0.0f;
        sm[OC2 + idx] = 0.0f;
    }
    __syncthreads();

    float* wb = sm + OHB + warp * 1024;   // warp staging (4 x 256 floats)
    float* gA = sm + OGA;
    float* gB = sm + OGB;

    // Region r: computes cell1(r) [r<TT] and cell2(r-1) [r>0].
    //   passA reads h1(r-1) (slot (r+2)%3)   [guarded by bar1 wait, target r*NB]
    //   passB reads h1(r-1) and h2(r-2) (slot (r+1)%3) [h2 guarded by bar2 (r-1)*NB]
    //   cell1 writes h1(r) (slot r%3); arrive bar1.
    //   cell2 writes h2(r-1) (slot (r+2)%3) + out(r-1) atomics; arrive bar2.
    // Triple buffering makes the cross-region WAR safe: a block past the
    // bar1(r-1) wait implies every block finished region r-2 entirely.
    for (int r = 0; r <= TT; r++) {
        const int q1 = (r + 2) % 3;     // h1(r-1)
        const int q2 = (r + 1) % 3;     // h2(r-2)
        const int w1 = r % 3;           // h1(r)
        const int w2 = (r + 2) % 3;     // h2(r-1)
        const bool prompt = (r < T_IN);

        if (r > 0) bar_wait(&g_bar1, (unsigned)r * NB);

        ull acc[8][4];

        // ---- pass A: gates1(r) = W_hh1 . h1(r-1)
        if (r < TT) {
            #pragma unroll
            for (int a = 0; a < 8; a++)
                #pragma unroll
                for (int q = 0; q < 4; q++) acc[a][q] = 0ull;
            pass_accum(g_h1[q1], sm + OW1, wb, acc, rg8, bg8, slice, lane);
            reduce_to_gbuf(acc, gA, rg8, bg8, lane);
        }

        // ---- prompt: cell1 early, so bar1 arrives mid-region (hidden)
        if (prompt) {
            __syncthreads();                        // gA complete
            float xv = x[cb * T_IN + r];
            float gi = gA[(cu)      * BAT + cb] + xv * sm[OCW1 + cu]      + sm[OCB1 + cu];
            float gf = gA[(4 + cu)  * BAT + cb] + xv * sm[OCW1 + 4 + cu]  + sm[OCB1 + 4 + cu];
            float gg = gA[(8 + cu)  * BAT + cb] + xv * sm[OCW1 + 8 + cu]  + sm[OCB1 + 8 + cu];
            float go = gA[(12 + cu) * BAT + cb] + xv * sm[OCW1 + 12 + cu] + sm[OCB1 + 12 + cu];
            float cc = sm[OC1 + cu * BAT + cb];
            float cn = sigf(gf) * cc + sigf(gi) * tanhf(gg);
            float hn = sigf(go) * tanhf(cn);
            sm[OC1 + cu * BAT + cb] = cn;
            g_h1[w1][(blk * 4 + cu) * BAT + cb] = hn;
            bar_arrive(&g_bar1);                    // publish h1(r)
        }

        // ---- passes B + cell2 (step r-1)
        if (r > 0) {
            #pragma unroll
            for (int a = 0; a < 8; a++)
                #pragma unroll
                for (int q = 0; q < 4; q++) acc[a][q] = 0ull;
            pass_accum(g_h1[q1], sm + OW2, wb, acc, rg8, bg8, slice, lane);
            if (r >= 2) bar_wait(&g_bar2, (unsigned)(r - 1) * NB);  // h2(r-2) ready
            pass_accum(g_h2[q2], sm + OW3, wb, acc, rg8, bg8, slice, lane);
            reduce_to_gbuf(acc, gB, rg8, bg8, lane);
            __syncthreads();

            float gi = gB[(cu)      * BAT + cb] + sm[OCB2 + cu];
            float gf = gB[(4 + cu)  * BAT + cb] + sm[OCB2 + 4 + cu];
            float gg = gB[(8 + cu)  * BAT + cb] + sm[OCB2 + 8 + cu];
            float go = gB[(12 + cu) * BAT + cb] + sm[OCB2 + 12 + cu];
            float cc = sm[OC2 + cu * BAT + cb];
            float cn = sigf(gf) * cc + sigf(gi) * tanhf(gg);
            float hn = sigf(go) * tanhf(cn);
            sm[OC2 + cu * BAT + cb] = cn;
            g_h2[w2][(blk * 4 + cu) * BAT + cb] = hn;
            gB[cu * BAT + cb] = hn * sm[OCWO + cu];   // own gate-i slot: safe
            __syncthreads();
            if (tid < BAT) {
                float v = gB[tid] + gB[BAT + tid] + gB[2 * BAT + tid] + gB[3 * BAT + tid];
                atomicAdd(&out[tid * TT + (r - 1)], v);
            }
            if (r < TT) bar_arrive(&g_bar2);        // publish h2(r-1) + out(r-1)
        }

        // ---- future: cell1 late (x = out(r-1) needs all blocks' atomics)
        if (!prompt && r < TT) {
            bar_wait(&g_bar2, (unsigned)r * NB);    // serial: inherent to feedback
            float xv = ldcg32(&out[cb * TT + (r - 1)]);
            float gi = gA[(cu)      * BAT + cb] + xv * sm[OCW1 + cu]      + sm[OCB1 + cu];
            float gf = gA[(4 + cu)  * BAT + cb] + xv * sm[OCW1 + 4 + cu]  + sm[OCB1 + 4 + cu];
            float gg = gA[(8 + cu)  * BAT + cb] + xv * sm[OCW1 + 8 + cu]  + sm[OCB1 + 8 + cu];
            float go = gA[(12 + cu) * BAT + cb] + xv * sm[OCW1 + 12 + cu] + sm[OCB1 + 12 + cu];
            float cc = sm[OC1 + cu * BAT + cb];
            float cn = sigf(gf) * cc + sigf(gi) * tanhf(gg);
            float hn = sigf(go) * tanhf(cn);
            sm[OC1 + cu * BAT + cb] = cn;
            g_h1[w1][(blk * 4 + cu) * BAT + cb] = hn;
            bar_arrive(&g_bar1);
        }
    }
}

extern "C" void kernel_launch(void* const* d_in, const int* in_sizes, int n_in,
                              void* d_out, int out_size) {
    const float* x     = (const float*)d_in[0];
    const float* W_ih1 = (const float*)d_in[1];
    const float* W_hh1 = (const float*)d_in[2];
    const float* b_ih1 = (const float*)d_in[3];
    const float* b_hh1 = (const float*)d_in[4];
    const float* W_ih2 = (const float*)d_in[5];
    const float* W_hh2 = (const float*)d_in[6];
    const float* b_ih2 = (const float*)d_in[7];
    const float* b_hh2 = (const float*)d_in[8];
    const float* W_out = (const float*)d_in[9];
    const float* b_out = (const float*)d_in[10];
    float* out = (float*)d_out;

    cudaFuncSetAttribute(lstm_persistent_kernel,
                         cudaFuncAttributeMaxDynamicSharedMemorySize, SMF * 4);

    init_kernel<<<(BAT * TT + 255) / 256, 256>>>(out, b_out);
    lstm_persistent_kernel<<<NB, TPB, SMF * 4>>>(
        x, W_ih1, W_hh1, b_ih1, b_hh1,
        W_ih2, W_hh2, b_ih2, b_hh2, W_out, out);
}